// round 5
// baseline (speedup 1.0000x reference)
#include <cuda_runtime.h>
#include <cstdint>

#define N_NODES 50000
#define DIM 128
#define ODIM 64
#define E_CAP 1048576
#define NB_SCAN ((N_NODES + 1023) / 1024)   // 49

// Scratch (static device globals; no allocation).
__device__ float g_h[(size_t)N_NODES * DIM];     // activations buffer A
__device__ float g_agg[(size_t)N_NODES * DIM];   // activations buffer B
__device__ float g_norm_src[N_NODES];
__device__ float g_norm_dst[N_NODES];
__device__ int   g_indeg[N_NODES];
__device__ int   g_outdeg[N_NODES];
__device__ int   g_incl[N_NODES];                // block-inclusive scan temp
__device__ int   g_btot[64];
__device__ int   g_rowstart[N_NODES];
__device__ int   g_cursor[N_NODES];
__device__ int   g_esrc[E_CAP];                  // CSR: src ids sorted by dst

// ---------------------------------------------------------------------------
// Degrees
// ---------------------------------------------------------------------------
__global__ void zero_deg_kernel() {
    int i = blockIdx.x * blockDim.x + threadIdx.x;
    if (i < N_NODES) { g_indeg[i] = 0; g_outdeg[i] = 0; }
}

__global__ void deg_kernel(const int* __restrict__ src, const int* __restrict__ dst, int E) {
    int i = blockIdx.x * blockDim.x + threadIdx.x;
    if (i < E) {
        atomicAdd(&g_outdeg[src[i]], 1);
        atomicAdd(&g_indeg[dst[i]], 1);
    }
}

// ---------------------------------------------------------------------------
// Scan step 1: per-block (1024) inclusive scan of indeg; publish block totals.
// ---------------------------------------------------------------------------
__global__ void scan1_kernel() {
    __shared__ int sm[1024];
    int idx = blockIdx.x * 1024 + threadIdx.x;
    int v = (idx < N_NODES) ? g_indeg[idx] : 0;
    sm[threadIdx.x] = v;
    __syncthreads();
#pragma unroll
    for (int off = 1; off < 1024; off <<= 1) {
        int t = (threadIdx.x >= off) ? sm[threadIdx.x - off] : 0;
        __syncthreads();
        sm[threadIdx.x] += t;
        __syncthreads();
    }
    if (idx < N_NODES) g_incl[idx] = sm[threadIdx.x];
    if (threadIdx.x == 1023) g_btot[blockIdx.x] = sm[1023];
}

// ---------------------------------------------------------------------------
// Scan step 2: each block inlines the 49-element block-total prefix (thread 0),
// then writes rowstart/cursor/norms. No inter-block waiting, no extra launch.
// ---------------------------------------------------------------------------
__global__ void scan3_kernel() {
    __shared__ int s_boff;
    int idx = blockIdx.x * blockDim.x + threadIdx.x;
    int sb = idx >> 10;   // which scan1 block this node belongs to (uniform per 256-block? no!)
    // blockDim=256 -> all threads in this block share the same (idx>>10) only if
    // the block doesn't straddle a 1024 boundary; 256 divides 1024, so sb is uniform.
    if (threadIdx.x == 0) {
        int s = 0;
        for (int b = 0; b < sb; b++) s += g_btot[b];
        s_boff = s;
    }
    __syncthreads();
    if (idx >= N_NODES) return;
    int ind = g_indeg[idx];
    int excl = g_incl[idx] - ind + s_boff;
    g_rowstart[idx] = excl;
    g_cursor[idx]   = excl;
    g_norm_dst[idx] = rsqrtf(fmaxf((float)ind, 1.f));
    g_norm_src[idx] = rsqrtf(fmaxf((float)g_outdeg[idx], 1.f));
}

__global__ void place_kernel(const int* __restrict__ src, const int* __restrict__ dst, int E) {
    int e = blockIdx.x * blockDim.x + threadIdx.x;
    if (e >= E) return;
    int d = dst[e];
    int pos = atomicAdd(&g_cursor[d], 1);
    if (pos < E_CAP) g_esrc[pos] = src[e];
}

// ---------------------------------------------------------------------------
// TF32 helpers
// ---------------------------------------------------------------------------
__device__ __forceinline__ uint32_t f2tf32(float f) {
    uint32_t r;
    asm("cvt.rna.tf32.f32 %0, %1;" : "=r"(r) : "f"(f));
    return r;
}

__device__ __forceinline__ void mma_tf32(float c[4], const uint32_t a[4], const uint32_t b[2]) {
    asm volatile(
        "mma.sync.aligned.m16n8k8.row.col.f32.tf32.tf32.f32 "
        "{%0,%1,%2,%3}, {%4,%5,%6,%7}, {%8,%9}, {%0,%1,%2,%3};"
        : "+f"(c[0]), "+f"(c[1]), "+f"(c[2]), "+f"(c[3])
        : "r"(a[0]), "r"(a[1]), "r"(a[2]), "r"(a[3]), "r"(b[0]), "r"(b[1]));
}

// ---------------------------------------------------------------------------
// Fused aggregate + GEMM (layers 1 & 2).
// Block = 128 dst nodes, 256 threads. Phase A: warp w aggregates nodes
// w*16..w*16+15 (register gather over CSR), writes tf32 directly into smem
// A-tile. Phase B: staged-W tf32 mma + epilogue.
// out = post * relu( [norm_dst * segsum((scale_src? norm_src:1) * x)] @ W + bias )
// ---------------------------------------------------------------------------
template <bool SCALE_SRC, bool POST>
__global__ void __launch_bounds__(256, 1)
fused_agg_gemm_kernel(const float* __restrict__ x,
                      const float* __restrict__ W,
                      const float* __restrict__ bias,
                      const float* __restrict__ post_scale,
                      float* __restrict__ out) {
    constexpr int K  = 128;
    constexpr int N  = 128;
    constexpr int SA = K + 4;
    constexpr int NT = N / 32;
    constexpr int ROWS = 128;

    extern __shared__ uint32_t smem[];
    uint32_t* sA = smem;               // [ROWS][SA]
    uint32_t* sW = smem + ROWS * SA;   // [N][SA]  (W transposed)

    const int tid  = threadIdx.x;
    const int row0 = blockIdx.x * ROWS;
    const int warp = tid >> 5;
    const int lane = tid & 31;

    // Stage W transposed (independent of aggregation).
#pragma unroll
    for (int i = tid; i < K * (N / 4); i += 256) {
        int k  = i / (N / 4);
        int nb = i % (N / 4);
        float4 v = __ldg(reinterpret_cast<const float4*>(W + (size_t)k * N) + nb);
        sW[(nb * 4 + 0) * SA + k] = f2tf32(v.x);
        sW[(nb * 4 + 1) * SA + k] = f2tf32(v.y);
        sW[(nb * 4 + 2) * SA + k] = f2tf32(v.z);
        sW[(nb * 4 + 3) * SA + k] = f2tf32(v.w);
    }

    // Phase A: aggregate 16 nodes per warp directly into sA (tf32).
    const float4* X = reinterpret_cast<const float4*>(x);
#pragma unroll 1
    for (int r = warp * 16; r < warp * 16 + 16; r++) {
        int node = row0 + r;
        float4 acc = make_float4(0.f, 0.f, 0.f, 0.f);
        if (node < N_NODES) {
            int beg = g_rowstart[node];
            int end = beg + g_indeg[node];
            int i = beg;
            for (; i + 4 <= end; i += 4) {
                int s0 = __ldg(g_esrc + i + 0);
                int s1 = __ldg(g_esrc + i + 1);
                int s2 = __ldg(g_esrc + i + 2);
                int s3 = __ldg(g_esrc + i + 3);
                float4 v0 = __ldg(X + (size_t)s0 * 32 + lane);
                float4 v1 = __ldg(X + (size_t)s1 * 32 + lane);
                float4 v2 = __ldg(X + (size_t)s2 * 32 + lane);
                float4 v3 = __ldg(X + (size_t)s3 * 32 + lane);
                float c0 = SCALE_SRC ? __ldg(g_norm_src + s0) : 1.f;
                float c1 = SCALE_SRC ? __ldg(g_norm_src + s1) : 1.f;
                float c2 = SCALE_SRC ? __ldg(g_norm_src + s2) : 1.f;
                float c3 = SCALE_SRC ? __ldg(g_norm_src + s3) : 1.f;
                acc.x = fmaf(c0, v0.x, acc.x); acc.y = fmaf(c0, v0.y, acc.y);
                acc.z = fmaf(c0, v0.z, acc.z); acc.w = fmaf(c0, v0.w, acc.w);
                acc.x = fmaf(c1, v1.x, acc.x); acc.y = fmaf(c1, v1.y, acc.y);
                acc.z = fmaf(c1, v1.z, acc.z); acc.w = fmaf(c1, v1.w, acc.w);
                acc.x = fmaf(c2, v2.x, acc.x); acc.y = fmaf(c2, v2.y, acc.y);
                acc.z = fmaf(c2, v2.z, acc.z); acc.w = fmaf(c2, v2.w, acc.w);
                acc.x = fmaf(c3, v3.x, acc.x); acc.y = fmaf(c3, v3.y, acc.y);
                acc.z = fmaf(c3, v3.z, acc.z); acc.w = fmaf(c3, v3.w, acc.w);
            }
            for (; i < end; i++) {
                int s = __ldg(g_esrc + i);
                float4 v = __ldg(X + (size_t)s * 32 + lane);
                float c = SCALE_SRC ? __ldg(g_norm_src + s) : 1.f;
                acc.x = fmaf(c, v.x, acc.x); acc.y = fmaf(c, v.y, acc.y);
                acc.z = fmaf(c, v.z, acc.z); acc.w = fmaf(c, v.w, acc.w);
            }
            float nd = g_norm_dst[node];
            acc.x *= nd; acc.y *= nd; acc.z *= nd; acc.w *= nd;
        }
        uint32_t* p = sA + r * SA + lane * 4;
        p[0] = f2tf32(acc.x); p[1] = f2tf32(acc.y);
        p[2] = f2tf32(acc.z); p[3] = f2tf32(acc.w);
    }
    __syncthreads();

    // Phase B: mma. 8 warps = 2 m-groups x 4 n-groups.
    const int warp_m = warp >> 2;
    const int warp_n = warp & 3;
    const int g      = lane >> 2;
    const int tg     = lane & 3;
    const int rbase  = warp_m * 64;
    const int ncol0  = warp_n * (N / 4);

    float acc[4][NT][4];
#pragma unroll
    for (int m = 0; m < 4; m++)
#pragma unroll
        for (int n = 0; n < NT; n++) {
            acc[m][n][0] = 0.f; acc[m][n][1] = 0.f; acc[m][n][2] = 0.f; acc[m][n][3] = 0.f;
        }

#pragma unroll
    for (int k0 = 0; k0 < K; k0 += 8) {
        uint32_t a[4][4];
#pragma unroll
        for (int m = 0; m < 4; m++) {
            const uint32_t* base = sA + (rbase + m * 16 + g) * SA + k0 + tg;
            a[m][0] = base[0];
            a[m][1] = base[8 * SA];
            a[m][2] = base[4];
            a[m][3] = base[8 * SA + 4];
        }
        uint32_t b[NT][2];
#pragma unroll
        for (int n = 0; n < NT; n++) {
            const uint32_t* base = sW + (ncol0 + n * 8 + g) * SA + k0 + tg;
            b[n][0] = base[0];
            b[n][1] = base[4];
        }
#pragma unroll
        for (int m = 0; m < 4; m++)
#pragma unroll
            for (int n = 0; n < NT; n++)
                mma_tf32(acc[m][n], a[m], b[n]);
    }

#pragma unroll
    for (int m = 0; m < 4; m++) {
#pragma unroll
        for (int half = 0; half < 2; half++) {
            int row = row0 + rbase + m * 16 + g + half * 8;
            if (row >= N_NODES) continue;
            float ps = POST ? __ldg(&post_scale[row]) : 1.f;
#pragma unroll
            for (int n = 0; n < NT; n++) {
                int col = ncol0 + n * 8 + 2 * tg;
                float2 o;
                o.x = acc[m][n][half * 2 + 0];
                o.y = acc[m][n][half * 2 + 1];
                float2 bv = *reinterpret_cast<const float2*>(bias + col);
                o.x += bv.x; o.y += bv.y;
                o.x = fmaxf(o.x, 0.f); o.y = fmaxf(o.y, 0.f);
                if (POST) { o.x *= ps; o.y *= ps; }
                *reinterpret_cast<float2*>(out + (size_t)row * N + col) = o;
            }
        }
    }
}

// ---------------------------------------------------------------------------
// Standalone GEMM for layer 3: t = norm_src * (in @ W3), N=64, no bias/relu.
// ---------------------------------------------------------------------------
__global__ void __launch_bounds__(256, 1)
gemm3_kernel(const float* __restrict__ in,
             const float* __restrict__ W,
             const float* __restrict__ post_scale,
             float* __restrict__ out) {
    constexpr int K  = 128;
    constexpr int N  = 64;
    constexpr int SA = K + 4;
    constexpr int NT = N / 32;     // 2
    constexpr int ROWS = 128;

    extern __shared__ uint32_t smem[];
    uint32_t* sA = smem;
    uint32_t* sW = smem + ROWS * SA;

    const int tid  = threadIdx.x;
    const int row0 = blockIdx.x * ROWS;

#pragma unroll
    for (int i = tid; i < ROWS * (K / 4); i += 256) {
        int r  = i / (K / 4);
        int kk = i % (K / 4);
        int row = row0 + r;
        float4 v = make_float4(0.f, 0.f, 0.f, 0.f);
        if (row < N_NODES)
            v = __ldg(reinterpret_cast<const float4*>(in + (size_t)row * K) + kk);
        uint32_t* p = sA + r * SA + kk * 4;
        p[0] = f2tf32(v.x); p[1] = f2tf32(v.y); p[2] = f2tf32(v.z); p[3] = f2tf32(v.w);
    }
#pragma unroll
    for (int i = tid; i < K * (N / 4); i += 256) {
        int k  = i / (N / 4);
        int nb = i % (N / 4);
        float4 v = __ldg(reinterpret_cast<const float4*>(W + (size_t)k * N) + nb);
        sW[(nb * 4 + 0) * SA + k] = f2tf32(v.x);
        sW[(nb * 4 + 1) * SA + k] = f2tf32(v.y);
        sW[(nb * 4 + 2) * SA + k] = f2tf32(v.z);
        sW[(nb * 4 + 3) * SA + k] = f2tf32(v.w);
    }
    __syncthreads();

    const int warp   = tid >> 5;
    const int lane   = tid & 31;
    const int warp_m = warp >> 2;
    const int warp_n = warp & 3;
    const int g      = lane >> 2;
    const int tg     = lane & 3;
    const int rbase  = warp_m * 64;
    const int ncol0  = warp_n * (N / 4);

    float acc[4][NT][4];
#pragma unroll
    for (int m = 0; m < 4; m++)
#pragma unroll
        for (int n = 0; n < NT; n++) {
            acc[m][n][0] = 0.f; acc[m][n][1] = 0.f; acc[m][n][2] = 0.f; acc[m][n][3] = 0.f;
        }

#pragma unroll
    for (int k0 = 0; k0 < K; k0 += 8) {
        uint32_t a[4][4];
#pragma unroll
        for (int m = 0; m < 4; m++) {
            const uint32_t* base = sA + (rbase + m * 16 + g) * SA + k0 + tg;
            a[m][0] = base[0];
            a[m][1] = base[8 * SA];
            a[m][2] = base[4];
            a[m][3] = base[8 * SA + 4];
        }
        uint32_t b[NT][2];
#pragma unroll
        for (int n = 0; n < NT; n++) {
            const uint32_t* base = sW + (ncol0 + n * 8 + g) * SA + k0 + tg;
            b[n][0] = base[0];
            b[n][1] = base[4];
        }
#pragma unroll
        for (int m = 0; m < 4; m++)
#pragma unroll
            for (int n = 0; n < NT; n++)
                mma_tf32(acc[m][n], a[m], b[n]);
    }

#pragma unroll
    for (int m = 0; m < 4; m++) {
#pragma unroll
        for (int half = 0; half < 2; half++) {
            int row = row0 + rbase + m * 16 + g + half * 8;
            if (row >= N_NODES) continue;
            float ps = __ldg(&post_scale[row]);
#pragma unroll
            for (int n = 0; n < NT; n++) {
                int col = ncol0 + n * 8 + 2 * tg;
                float2 o;
                o.x = acc[m][n][half * 2 + 0] * ps;
                o.y = acc[m][n][half * 2 + 1] * ps;
                *reinterpret_cast<float2*>(out + (size_t)row * N + col) = o;
            }
        }
    }
}

// ---------------------------------------------------------------------------
// Final CSR aggregation, 64 dims: two nodes per warp, + bias epilogue.
// out[n] = norm_dst[n] * segsum(x) + b3
// ---------------------------------------------------------------------------
__global__ void agg64_kernel(const float* __restrict__ x,
                             const float* __restrict__ b3,
                             float* __restrict__ out) {
    int w = (blockIdx.x * blockDim.x + threadIdx.x) >> 5;
    int sub = (threadIdx.x >> 4) & 1;
    int lane = threadIdx.x & 15;
    int n = w * 2 + sub;
    if (n >= N_NODES) return;
    int beg = g_rowstart[n];
    int end = beg + g_indeg[n];
    const float4* X = reinterpret_cast<const float4*>(x);
    float4 acc = make_float4(0.f, 0.f, 0.f, 0.f);

    int i = beg;
    for (; i + 4 <= end; i += 4) {
        int s0 = __ldg(g_esrc + i + 0);
        int s1 = __ldg(g_esrc + i + 1);
        int s2 = __ldg(g_esrc + i + 2);
        int s3 = __ldg(g_esrc + i + 3);
        float4 v0 = __ldg(X + (size_t)s0 * 16 + lane);
        float4 v1 = __ldg(X + (size_t)s1 * 16 + lane);
        float4 v2 = __ldg(X + (size_t)s2 * 16 + lane);
        float4 v3 = __ldg(X + (size_t)s3 * 16 + lane);
        acc.x += v0.x + v1.x + v2.x + v3.x;
        acc.y += v0.y + v1.y + v2.y + v3.y;
        acc.z += v0.z + v1.z + v2.z + v3.z;
        acc.w += v0.w + v1.w + v2.w + v3.w;
    }
    for (; i < end; i++) {
        int s = __ldg(g_esrc + i);
        float4 v = __ldg(X + (size_t)s * 16 + lane);
        acc.x += v.x; acc.y += v.y; acc.z += v.z; acc.w += v.w;
    }
    float nd = g_norm_dst[n];
    float4 b = __ldg(reinterpret_cast<const float4*>(b3) + lane);
    float4 o;
    o.x = fmaf(acc.x, nd, b.x);
    o.y = fmaf(acc.y, nd, b.y);
    o.z = fmaf(acc.z, nd, b.z);
    o.w = fmaf(acc.w, nd, b.w);
    reinterpret_cast<float4*>(out)[(size_t)n * 16 + lane] = o;
}

// ---------------------------------------------------------------------------
extern "C" void kernel_launch(void* const* d_in, const int* in_sizes, int n_in,
                              void* d_out, int out_size) {
    const float* features = (const float*)d_in[0];
    const float* W1 = (const float*)d_in[1];
    const float* b1 = (const float*)d_in[2];
    const float* W2 = (const float*)d_in[3];
    const float* b2 = (const float*)d_in[4];
    const float* W3 = (const float*)d_in[5];
    const float* b3 = (const float*)d_in[6];
    const int* src  = (const int*)d_in[7];
    const int* dst  = (const int*)d_in[8];
    const int E = in_sizes[7];
    float* out = (float*)d_out;

    float *h, *agg, *nsrc;
    cudaGetSymbolAddress((void**)&h,    g_h);
    cudaGetSymbolAddress((void**)&agg,  g_agg);
    cudaGetSymbolAddress((void**)&nsrc, g_norm_src);

    const int smem128 = (128 + 128) * 132 * 4;   // 135168
    const int smem64  = (128 + 64)  * 132 * 4;   // 101376
    cudaFuncSetAttribute(fused_agg_gemm_kernel<true, true>,
                         cudaFuncAttributeMaxDynamicSharedMemorySize, smem128);
    cudaFuncSetAttribute(fused_agg_gemm_kernel<false, false>,
                         cudaFuncAttributeMaxDynamicSharedMemorySize, smem128);
    cudaFuncSetAttribute(gemm3_kernel,
                         cudaFuncAttributeMaxDynamicSharedMemorySize, smem64);

    const int TB = 256;
    const int blocks128 = (N_NODES + 127) / 128;   // 391

    // CSR build (sorted by dst) + norms: 5 launches, no inter-block waits.
    zero_deg_kernel<<<(N_NODES + TB - 1) / TB, TB>>>();
    deg_kernel<<<(E + TB - 1) / TB, TB>>>(src, dst, E);
    scan1_kernel<<<NB_SCAN, 1024>>>();
    scan3_kernel<<<(N_NODES + TB - 1) / TB, TB>>>();
    place_kernel<<<(E + TB - 1) / TB, TB>>>(src, dst, E);

    // Layer 1 (fused): h = norm_src * relu((norm_dst*segsum(norm_src*features)) @ W1 + b1)
    fused_agg_gemm_kernel<true, true>
        <<<blocks128, 256, smem128>>>(features, W1, b1, nsrc, h);

    // Layer 2 (fused): agg = relu((norm_dst*segsum(h)) @ W2 + b2)
    fused_agg_gemm_kernel<false, false>
        <<<blocks128, 256, smem128>>>(h, W2, b2, nullptr, agg);

    // Layer 3 (reordered): t = norm_src * (agg @ W3) -> g_h; out = norm_dst*segsum(t)+b3
    gemm3_kernel<<<blocks128, 256, smem64>>>(agg, W3, nsrc, h);
    agg64_kernel<<<((N_NODES + 1) / 2 * 32 + TB - 1) / TB, TB>>>(h, b3, out);
}

// round 6
// speedup vs baseline: 1.7129x; 1.7129x over previous
#include <cuda_runtime.h>
#include <cuda_fp16.h>
#include <cstdint>

#define N_NODES 50000
#define DIM 128
#define ODIM 64
#define E_CAP 1048576
#define NB_SCAN ((N_NODES + 1023) / 1024)   // 49

// Scratch (static device globals; no allocation).
__device__ float g_h[(size_t)N_NODES * DIM];     // fp32 activations
__device__ float g_agg[(size_t)N_NODES * DIM];   // fp32 aggregation buffer
__device__ __align__(16) __half g_hh[(size_t)N_NODES * DIM];  // fp16 activations
__device__ float g_norm_src[N_NODES];
__device__ float g_norm_dst[N_NODES];
__device__ int   g_indeg[N_NODES];
__device__ int   g_outdeg[N_NODES];
__device__ int   g_incl[N_NODES];                // block-inclusive scan temp
__device__ int   g_btot[64];
__device__ int   g_rowstart[N_NODES];
__device__ int   g_cursor[N_NODES];
__device__ int   g_esrc[E_CAP];                  // CSR: src ids sorted by dst

// ---------------------------------------------------------------------------
// Degrees
// ---------------------------------------------------------------------------
__global__ void zero_deg_kernel() {
    int i = blockIdx.x * blockDim.x + threadIdx.x;
    if (i < N_NODES) { g_indeg[i] = 0; g_outdeg[i] = 0; }
}

__global__ void deg_kernel(const int* __restrict__ src, const int* __restrict__ dst, int E) {
    int i = blockIdx.x * blockDim.x + threadIdx.x;
    if (i < E) {
        atomicAdd(&g_outdeg[src[i]], 1);
        atomicAdd(&g_indeg[dst[i]], 1);
    }
}

// ---------------------------------------------------------------------------
// Scan step 1: per-block (1024) inclusive scan of indeg; publish block totals.
// ---------------------------------------------------------------------------
__global__ void scan1_kernel() {
    __shared__ int sm[1024];
    int idx = blockIdx.x * 1024 + threadIdx.x;
    int v = (idx < N_NODES) ? g_indeg[idx] : 0;
    sm[threadIdx.x] = v;
    __syncthreads();
#pragma unroll
    for (int off = 1; off < 1024; off <<= 1) {
        int t = (threadIdx.x >= off) ? sm[threadIdx.x - off] : 0;
        __syncthreads();
        sm[threadIdx.x] += t;
        __syncthreads();
    }
    if (idx < N_NODES) g_incl[idx] = sm[threadIdx.x];
    if (threadIdx.x == 1023) g_btot[blockIdx.x] = sm[1023];
}

// ---------------------------------------------------------------------------
// Scan step 2: each block computes its block-total prefix with a PARALLEL
// warp reduction (49 values), then writes rowstart/cursor/norms.
// ---------------------------------------------------------------------------
__global__ void scan3_kernel() {
    __shared__ int s_boff;
    const int sb = blockIdx.x >> 2;  // 256 threads/block, 1024 per scan1 block
    if (threadIdx.x < 32) {
        int t = threadIdx.x;
        int v = (t < sb ? g_btot[t] : 0) + (t + 32 < sb ? g_btot[t + 32] : 0);
#pragma unroll
        for (int o = 16; o; o >>= 1) v += __shfl_down_sync(0xffffffffu, v, o);
        if (t == 0) s_boff = v;
    }
    __syncthreads();
    int idx = blockIdx.x * blockDim.x + threadIdx.x;
    if (idx >= N_NODES) return;
    int ind = g_indeg[idx];
    int excl = g_incl[idx] - ind + s_boff;
    g_rowstart[idx] = excl;
    g_cursor[idx]   = excl;
    g_norm_dst[idx] = rsqrtf(fmaxf((float)ind, 1.f));
    g_norm_src[idx] = rsqrtf(fmaxf((float)g_outdeg[idx], 1.f));
}

__global__ void place_kernel(const int* __restrict__ src, const int* __restrict__ dst, int E) {
    int e = blockIdx.x * blockDim.x + threadIdx.x;
    if (e >= E) return;
    int d = dst[e];
    int pos = atomicAdd(&g_cursor[d], 1);
    if (pos < E_CAP) g_esrc[pos] = src[e];
}

// ---------------------------------------------------------------------------
// CSR aggregation, 128 dims fp32 input (layer 1): one warp per dst node.
// agg[n] = norm_dst[n] * sum_{s in N(n)} norm_src[s] * x[s]
// ---------------------------------------------------------------------------
__global__ void agg128_f32_kernel(const float* __restrict__ x, float* __restrict__ agg) {
    int w = (blockIdx.x * blockDim.x + threadIdx.x) >> 5;
    if (w >= N_NODES) return;
    int lane = threadIdx.x & 31;
    int beg = g_rowstart[w];
    int end = beg + g_indeg[w];
    const float4* X = reinterpret_cast<const float4*>(x);
    float4 acc = make_float4(0.f, 0.f, 0.f, 0.f);

    int i = beg;
    for (; i + 4 <= end; i += 4) {
        int s0 = __ldg(g_esrc + i + 0);
        int s1 = __ldg(g_esrc + i + 1);
        int s2 = __ldg(g_esrc + i + 2);
        int s3 = __ldg(g_esrc + i + 3);
        float4 v0 = __ldg(X + (size_t)s0 * 32 + lane);
        float4 v1 = __ldg(X + (size_t)s1 * 32 + lane);
        float4 v2 = __ldg(X + (size_t)s2 * 32 + lane);
        float4 v3 = __ldg(X + (size_t)s3 * 32 + lane);
        float c0 = __ldg(g_norm_src + s0);
        float c1 = __ldg(g_norm_src + s1);
        float c2 = __ldg(g_norm_src + s2);
        float c3 = __ldg(g_norm_src + s3);
        acc.x = fmaf(c0, v0.x, acc.x); acc.y = fmaf(c0, v0.y, acc.y);
        acc.z = fmaf(c0, v0.z, acc.z); acc.w = fmaf(c0, v0.w, acc.w);
        acc.x = fmaf(c1, v1.x, acc.x); acc.y = fmaf(c1, v1.y, acc.y);
        acc.z = fmaf(c1, v1.z, acc.z); acc.w = fmaf(c1, v1.w, acc.w);
        acc.x = fmaf(c2, v2.x, acc.x); acc.y = fmaf(c2, v2.y, acc.y);
        acc.z = fmaf(c2, v2.z, acc.z); acc.w = fmaf(c2, v2.w, acc.w);
        acc.x = fmaf(c3, v3.x, acc.x); acc.y = fmaf(c3, v3.y, acc.y);
        acc.z = fmaf(c3, v3.z, acc.z); acc.w = fmaf(c3, v3.w, acc.w);
    }
    for (; i < end; i++) {
        int s = __ldg(g_esrc + i);
        float4 v = __ldg(X + (size_t)s * 32 + lane);
        float c = __ldg(g_norm_src + s);
        acc.x = fmaf(c, v.x, acc.x); acc.y = fmaf(c, v.y, acc.y);
        acc.z = fmaf(c, v.z, acc.z); acc.w = fmaf(c, v.w, acc.w);
    }
    float nd = g_norm_dst[w];
    acc.x *= nd; acc.y *= nd; acc.z *= nd; acc.w *= nd;
    reinterpret_cast<float4*>(agg)[(size_t)w * 32 + lane] = acc;
}

// ---------------------------------------------------------------------------
// CSR aggregation, 128 dims fp16 input (layer 2): one warp per dst node.
// Lane loads 8B (4 halves) per edge; fp32 accumulation.
// agg[n] = norm_dst[n] * sum x[s]
// ---------------------------------------------------------------------------
__global__ void agg128_f16_kernel(const __half* __restrict__ x, float* __restrict__ agg) {
    int w = (blockIdx.x * blockDim.x + threadIdx.x) >> 5;
    if (w >= N_NODES) return;
    int lane = threadIdx.x & 31;
    int beg = g_rowstart[w];
    int end = beg + g_indeg[w];
    const uint2* X = reinterpret_cast<const uint2*>(x);
    float4 acc = make_float4(0.f, 0.f, 0.f, 0.f);

    int i = beg;
    for (; i + 4 <= end; i += 4) {
        int s0 = __ldg(g_esrc + i + 0);
        int s1 = __ldg(g_esrc + i + 1);
        int s2 = __ldg(g_esrc + i + 2);
        int s3 = __ldg(g_esrc + i + 3);
        uint2 u0 = __ldg(X + (size_t)s0 * 32 + lane);
        uint2 u1 = __ldg(X + (size_t)s1 * 32 + lane);
        uint2 u2 = __ldg(X + (size_t)s2 * 32 + lane);
        uint2 u3 = __ldg(X + (size_t)s3 * 32 + lane);
#pragma unroll
        for (int j = 0; j < 4; j++) {
            uint2 u = (j == 0) ? u0 : (j == 1) ? u1 : (j == 2) ? u2 : u3;
            float2 a = __half22float2(*reinterpret_cast<__half2*>(&u.x));
            float2 b = __half22float2(*reinterpret_cast<__half2*>(&u.y));
            acc.x += a.x; acc.y += a.y; acc.z += b.x; acc.w += b.y;
        }
    }
    for (; i < end; i++) {
        int s = __ldg(g_esrc + i);
        uint2 u = __ldg(X + (size_t)s * 32 + lane);
        float2 a = __half22float2(*reinterpret_cast<__half2*>(&u.x));
        float2 b = __half22float2(*reinterpret_cast<__half2*>(&u.y));
        acc.x += a.x; acc.y += a.y; acc.z += b.x; acc.w += b.y;
    }
    float nd = g_norm_dst[w];
    acc.x *= nd; acc.y *= nd; acc.z *= nd; acc.w *= nd;
    reinterpret_cast<float4*>(agg)[(size_t)w * 32 + lane] = acc;
}

// ---------------------------------------------------------------------------
// Final CSR aggregation, 64 dims fp16 input: two nodes per warp, + b3 epilogue.
// out[n] = norm_dst[n] * segsum(t) + b3
// ---------------------------------------------------------------------------
__global__ void agg64_f16_kernel(const __half* __restrict__ x,
                                 const float* __restrict__ b3,
                                 float* __restrict__ out) {
    int w = (blockIdx.x * blockDim.x + threadIdx.x) >> 5;
    int sub = (threadIdx.x >> 4) & 1;
    int lane = threadIdx.x & 15;
    int n = w * 2 + sub;
    if (n >= N_NODES) return;
    int beg = g_rowstart[n];
    int end = beg + g_indeg[n];
    const uint2* X = reinterpret_cast<const uint2*>(x);
    float4 acc = make_float4(0.f, 0.f, 0.f, 0.f);

    int i = beg;
    for (; i + 4 <= end; i += 4) {
        int s0 = __ldg(g_esrc + i + 0);
        int s1 = __ldg(g_esrc + i + 1);
        int s2 = __ldg(g_esrc + i + 2);
        int s3 = __ldg(g_esrc + i + 3);
        uint2 u0 = __ldg(X + (size_t)s0 * 16 + lane);
        uint2 u1 = __ldg(X + (size_t)s1 * 16 + lane);
        uint2 u2 = __ldg(X + (size_t)s2 * 16 + lane);
        uint2 u3 = __ldg(X + (size_t)s3 * 16 + lane);
#pragma unroll
        for (int j = 0; j < 4; j++) {
            uint2 u = (j == 0) ? u0 : (j == 1) ? u1 : (j == 2) ? u2 : u3;
            float2 a = __half22float2(*reinterpret_cast<__half2*>(&u.x));
            float2 b = __half22float2(*reinterpret_cast<__half2*>(&u.y));
            acc.x += a.x; acc.y += a.y; acc.z += b.x; acc.w += b.y;
        }
    }
    for (; i < end; i++) {
        int s = __ldg(g_esrc + i);
        uint2 u = __ldg(X + (size_t)s * 16 + lane);
        float2 a = __half22float2(*reinterpret_cast<__half2*>(&u.x));
        float2 b = __half22float2(*reinterpret_cast<__half2*>(&u.y));
        acc.x += a.x; acc.y += a.y; acc.z += b.x; acc.w += b.y;
    }
    float nd = g_norm_dst[n];
    float4 b = __ldg(reinterpret_cast<const float4*>(b3) + lane);
    float4 o;
    o.x = fmaf(acc.x, nd, b.x);
    o.y = fmaf(acc.y, nd, b.y);
    o.z = fmaf(acc.z, nd, b.z);
    o.w = fmaf(acc.w, nd, b.w);
    reinterpret_cast<float4*>(out)[(size_t)n * 16 + lane] = o;
}

// ---------------------------------------------------------------------------
// TF32 helpers
// ---------------------------------------------------------------------------
__device__ __forceinline__ uint32_t f2tf32(float f) {
    uint32_t r;
    asm("cvt.rna.tf32.f32 %0, %1;" : "=r"(r) : "f"(f));
    return r;
}

__device__ __forceinline__ void mma_tf32(float c[4], const uint32_t a[4], const uint32_t b[2]) {
    asm volatile(
        "mma.sync.aligned.m16n8k8.row.col.f32.tf32.tf32.f32 "
        "{%0,%1,%2,%3}, {%4,%5,%6,%7}, {%8,%9}, {%0,%1,%2,%3};"
        : "+f"(c[0]), "+f"(c[1]), "+f"(c[2]), "+f"(c[3])
        : "r"(a[0]), "r"(a[1]), "r"(a[2]), "r"(a[3]), "r"(b[0]), "r"(b[1]));
}

// ---------------------------------------------------------------------------
// TF32 GEMM: out = post * act(in @ W + bias). fp32 in, fp32 or fp16 out.
// Block: 128 rows x N cols, 8 warps (2 m-groups x 4 n-groups).
// ---------------------------------------------------------------------------
template <int N, bool RELU, bool BIAS, bool POST, bool HALF_OUT>
__global__ void __launch_bounds__(256, 1)
gemm_tf32_kernel(const float* __restrict__ in,
                 const float* __restrict__ W,
                 const float* __restrict__ bias,
                 const float* __restrict__ post_scale,
                 void* __restrict__ out_v) {
    constexpr int K  = 128;
    constexpr int SA = K + 4;
    constexpr int NT = N / 32;
    constexpr int ROWS = 128;

    extern __shared__ uint32_t smem[];
    uint32_t* sA = smem;               // [ROWS][SA]
    uint32_t* sW = smem + ROWS * SA;   // [N][SA]  (W transposed)

    const int tid  = threadIdx.x;
    const int row0 = blockIdx.x * ROWS;

#pragma unroll
    for (int i = tid; i < ROWS * (K / 4); i += 256) {
        int r  = i / (K / 4);
        int kk = i % (K / 4);
        int row = row0 + r;
        float4 v = make_float4(0.f, 0.f, 0.f, 0.f);
        if (row < N_NODES)
            v = __ldg(reinterpret_cast<const float4*>(in + (size_t)row * K) + kk);
        uint32_t* p = sA + r * SA + kk * 4;
        p[0] = f2tf32(v.x); p[1] = f2tf32(v.y); p[2] = f2tf32(v.z); p[3] = f2tf32(v.w);
    }
#pragma unroll
    for (int i = tid; i < K * (N / 4); i += 256) {
        int k  = i / (N / 4);
        int nb = i % (N / 4);
        float4 v = __ldg(reinterpret_cast<const float4*>(W + (size_t)k * N) + nb);
        sW[(nb * 4 + 0) * SA + k] = f2tf32(v.x);
        sW[(nb * 4 + 1) * SA + k] = f2tf32(v.y);
        sW[(nb * 4 + 2) * SA + k] = f2tf32(v.z);
        sW[(nb * 4 + 3) * SA + k] = f2tf32(v.w);
    }
    __syncthreads();

    const int warp   = tid >> 5;
    const int lane   = tid & 31;
    const int warp_m = warp >> 2;
    const int warp_n = warp & 3;
    const int g      = lane >> 2;
    const int tg     = lane & 3;
    const int rbase  = warp_m * 64;
    const int ncol0  = warp_n * (N / 4);

    float acc[4][NT][4];
#pragma unroll
    for (int m = 0; m < 4; m++)
#pragma unroll
        for (int n = 0; n < NT; n++) {
            acc[m][n][0] = 0.f; acc[m][n][1] = 0.f; acc[m][n][2] = 0.f; acc[m][n][3] = 0.f;
        }

#pragma unroll
    for (int k0 = 0; k0 < K; k0 += 8) {
        uint32_t a[4][4];
#pragma unroll
        for (int m = 0; m < 4; m++) {
            const uint32_t* base = sA + (rbase + m * 16 + g) * SA + k0 + tg;
            a[m][0] = base[0];
            a[m][1] = base[8 * SA];
            a[m][2] = base[4];
            a[m][3] = base[8 * SA + 4];
        }
        uint32_t b[NT][2];
#pragma unroll
        for (int n = 0; n < NT; n++) {
            const uint32_t* base = sW + (ncol0 + n * 8 + g) * SA + k0 + tg;
            b[n][0] = base[0];
            b[n][1] = base[4];
        }
#pragma unroll
        for (int m = 0; m < 4; m++)
#pragma unroll
            for (int n = 0; n < NT; n++)
                mma_tf32(acc[m][n], a[m], b[n]);
    }

#pragma unroll
    for (int m = 0; m < 4; m++) {
#pragma unroll
        for (int half = 0; half < 2; half++) {
            int row = row0 + rbase + m * 16 + g + half * 8;
            if (row >= N_NODES) continue;
            float ps = POST ? __ldg(&post_scale[row]) : 1.f;
#pragma unroll
            for (int n = 0; n < NT; n++) {
                int col = ncol0 + n * 8 + 2 * tg;
                float ox = acc[m][n][half * 2 + 0];
                float oy = acc[m][n][half * 2 + 1];
                if (BIAS) {
                    float2 bv = *reinterpret_cast<const float2*>(bias + col);
                    ox += bv.x; oy += bv.y;
                }
                if (RELU) { ox = fmaxf(ox, 0.f); oy = fmaxf(oy, 0.f); }
                if (POST) { ox *= ps; oy *= ps; }
                if (HALF_OUT) {
                    __half2* o = reinterpret_cast<__half2*>(
                        static_cast<__half*>(out_v) + (size_t)row * N + col);
                    *o = __floats2half2_rn(ox, oy);
                } else {
                    float2* o = reinterpret_cast<float2*>(
                        static_cast<float*>(out_v) + (size_t)row * N + col);
                    *o = make_float2(ox, oy);
                }
            }
        }
    }
}

// ---------------------------------------------------------------------------
extern "C" void kernel_launch(void* const* d_in, const int* in_sizes, int n_in,
                              void* d_out, int out_size) {
    const float* features = (const float*)d_in[0];
    const float* W1 = (const float*)d_in[1];
    const float* b1 = (const float*)d_in[2];
    const float* W2 = (const float*)d_in[3];
    const float* b2 = (const float*)d_in[4];
    const float* W3 = (const float*)d_in[5];
    const float* b3 = (const float*)d_in[6];
    const int* src  = (const int*)d_in[7];
    const int* dst  = (const int*)d_in[8];
    const int E = in_sizes[7];
    float* out = (float*)d_out;

    float *h, *agg, *nsrc;
    __half* hh;
    cudaGetSymbolAddress((void**)&h,    g_h);
    cudaGetSymbolAddress((void**)&agg,  g_agg);
    cudaGetSymbolAddress((void**)&hh,   g_hh);
    cudaGetSymbolAddress((void**)&nsrc, g_norm_src);

    const int smem128 = (128 + 128) * 132 * 4;   // 135168
    const int smem64  = (128 + 64)  * 132 * 4;   // 101376
    cudaFuncSetAttribute(gemm_tf32_kernel<128, true,  true,  true,  true>,
                         cudaFuncAttributeMaxDynamicSharedMemorySize, smem128);
    cudaFuncSetAttribute(gemm_tf32_kernel<128, true,  true,  false, false>,
                         cudaFuncAttributeMaxDynamicSharedMemorySize, smem128);
    cudaFuncSetAttribute(gemm_tf32_kernel<64,  false, false, true,  true>,
                         cudaFuncAttributeMaxDynamicSharedMemorySize, smem64);

    const int TB = 256;
    const int blocks128 = (N_NODES + 127) / 128;   // 391

    // CSR build (sorted by dst) + norms.
    zero_deg_kernel<<<(N_NODES + TB - 1) / TB, TB>>>();
    deg_kernel<<<(E + TB - 1) / TB, TB>>>(src, dst, E);
    scan1_kernel<<<NB_SCAN, 1024>>>();
    scan3_kernel<<<(N_NODES + TB - 1) / TB, TB>>>();
    place_kernel<<<(E + TB - 1) / TB, TB>>>(src, dst, E);

    // Layer 1: agg = norm_dst*segsum(norm_src*features);
    //          hh(fp16) = norm_src * relu(agg @ W1 + b1)
    agg128_f32_kernel<<<(N_NODES * 32 + TB - 1) / TB, TB>>>(features, agg);
    gemm_tf32_kernel<128, true, true, true, true>
        <<<blocks128, 256, smem128>>>(agg, W1, b1, nsrc, hh);

    // Layer 2: agg = norm_dst*segsum(hh); h(fp32) = relu(agg @ W2 + b2)
    agg128_f16_kernel<<<(N_NODES * 32 + TB - 1) / TB, TB>>>(hh, agg);
    gemm_tf32_kernel<128, true, true, false, false>
        <<<blocks128, 256, smem128>>>(agg, W2, b2, nullptr, h);

    // Layer 3 (reordered): hh(fp16, 64-wide) = norm_src * (h @ W3);
    //                      out = norm_dst * segsum(hh) + b3
    gemm_tf32_kernel<64, false, false, true, true>
        <<<blocks128, 256, smem64>>>(h, W3, nullptr, nsrc, hh);
    agg64_f16_kernel<<<((N_NODES + 1) / 2 * 32 + TB - 1) / TB, TB>>>(hh, b3, out);
}

// round 7
// speedup vs baseline: 1.8429x; 1.0759x over previous
#include <cuda_runtime.h>
#include <cuda_fp16.h>
#include <cstdint>

#define N_NODES 50000
#define DIM 128
#define ODIM 64
#define E_CAP 1048576
#define NB_SCAN ((N_NODES + 1023) / 1024)   // 49

// Scratch (static device globals; no allocation).
__device__ float g_agg[(size_t)N_NODES * DIM];   // fp32 aggregation buffer
__device__ __align__(16) __half g_hh[(size_t)N_NODES * DIM];  // fp16 activations (phased reuse)
__device__ float g_norm_src[N_NODES];
__device__ float g_norm_dst[N_NODES];
__device__ int   g_indeg[N_NODES];
__device__ int   g_outdeg[N_NODES];
__device__ int   g_incl[N_NODES];                // block-inclusive scan temp
__device__ int   g_btot[64];
__device__ int   g_rowstart[N_NODES];
__device__ int   g_cursor[N_NODES];
__device__ int   g_esrc[E_CAP];                  // CSR: src ids sorted by dst

// ---------------------------------------------------------------------------
// Degrees
// ---------------------------------------------------------------------------
__global__ void zero_deg_kernel() {
    int i = blockIdx.x * blockDim.x + threadIdx.x;
    if (i < N_NODES) { g_indeg[i] = 0; g_outdeg[i] = 0; }
}

__global__ void deg_kernel(const int* __restrict__ src, const int* __restrict__ dst, int E) {
    int i = blockIdx.x * blockDim.x + threadIdx.x;
    if (i < E) {
        atomicAdd(&g_outdeg[src[i]], 1);
        atomicAdd(&g_indeg[dst[i]], 1);
    }
}

// ---------------------------------------------------------------------------
// Scan step 1: per-block (1024) inclusive scan of indeg; publish block totals.
// ---------------------------------------------------------------------------
__global__ void scan1_kernel() {
    __shared__ int sm[1024];
    int idx = blockIdx.x * 1024 + threadIdx.x;
    int v = (idx < N_NODES) ? g_indeg[idx] : 0;
    sm[threadIdx.x] = v;
    __syncthreads();
#pragma unroll
    for (int off = 1; off < 1024; off <<= 1) {
        int t = (threadIdx.x >= off) ? sm[threadIdx.x - off] : 0;
        __syncthreads();
        sm[threadIdx.x] += t;
        __syncthreads();
    }
    if (idx < N_NODES) g_incl[idx] = sm[threadIdx.x];
    if (threadIdx.x == 1023) g_btot[blockIdx.x] = sm[1023];
}

// ---------------------------------------------------------------------------
// Scan step 2: each block computes its block-total prefix with a parallel
// warp reduction (49 values), then writes rowstart/cursor/norms.
// ---------------------------------------------------------------------------
__global__ void scan3_kernel() {
    __shared__ int s_boff;
    const int sb = blockIdx.x >> 2;  // 256 threads/block, 1024 per scan1 block
    if (threadIdx.x < 32) {
        int t = threadIdx.x;
        int v = (t < sb ? g_btot[t] : 0) + (t + 32 < sb ? g_btot[t + 32] : 0);
#pragma unroll
        for (int o = 16; o; o >>= 1) v += __shfl_down_sync(0xffffffffu, v, o);
        if (t == 0) s_boff = v;
    }
    __syncthreads();
    int idx = blockIdx.x * blockDim.x + threadIdx.x;
    if (idx >= N_NODES) return;
    int ind = g_indeg[idx];
    int excl = g_incl[idx] - ind + s_boff;
    g_rowstart[idx] = excl;
    g_cursor[idx]   = excl;
    g_norm_dst[idx] = rsqrtf(fmaxf((float)ind, 1.f));
    g_norm_src[idx] = rsqrtf(fmaxf((float)g_outdeg[idx], 1.f));
}

__global__ void place_kernel(const int* __restrict__ src, const int* __restrict__ dst, int E) {
    int e = blockIdx.x * blockDim.x + threadIdx.x;
    if (e >= E) return;
    int d = dst[e];
    int pos = atomicAdd(&g_cursor[d], 1);
    if (pos < E_CAP) g_esrc[pos] = src[e];
}

// ---------------------------------------------------------------------------
// Convert features -> fp16 with norm_src pre-folded: hh[i] = h(norm_src[i]*f[i])
// Thread handles one float4 (4 elems).
// ---------------------------------------------------------------------------
__global__ void convert_feat_kernel(const float* __restrict__ f) {
    int t = blockIdx.x * blockDim.x + threadIdx.x;
    if (t >= N_NODES * DIM / 4) return;
    int row = t >> 5;  // /32 float4 per row
    float ns = __ldg(&g_norm_src[row]);
    float4 v = __ldg(reinterpret_cast<const float4*>(f) + t);
    __half2 a = __floats2half2_rn(v.x * ns, v.y * ns);
    __half2 b = __floats2half2_rn(v.z * ns, v.w * ns);
    uint2 u;
    u.x = *reinterpret_cast<uint32_t*>(&a);
    u.y = *reinterpret_cast<uint32_t*>(&b);
    reinterpret_cast<uint2*>(g_hh)[t] = u;
}

// ---------------------------------------------------------------------------
// CSR aggregation, 128 dims fp16 input: one warp per dst node, fp32 accum.
// agg[n] = norm_dst[n] * sum x[s]
// ---------------------------------------------------------------------------
__global__ void agg128_f16_kernel(const __half* __restrict__ x, float* __restrict__ agg) {
    int w = (blockIdx.x * blockDim.x + threadIdx.x) >> 5;
    if (w >= N_NODES) return;
    int lane = threadIdx.x & 31;
    int beg = g_rowstart[w];
    int end = beg + g_indeg[w];
    const uint2* X = reinterpret_cast<const uint2*>(x);
    float4 acc = make_float4(0.f, 0.f, 0.f, 0.f);

    int i = beg;
    for (; i + 4 <= end; i += 4) {
        int s0 = __ldg(g_esrc + i + 0);
        int s1 = __ldg(g_esrc + i + 1);
        int s2 = __ldg(g_esrc + i + 2);
        int s3 = __ldg(g_esrc + i + 3);
        uint2 u0 = __ldg(X + (size_t)s0 * 32 + lane);
        uint2 u1 = __ldg(X + (size_t)s1 * 32 + lane);
        uint2 u2 = __ldg(X + (size_t)s2 * 32 + lane);
        uint2 u3 = __ldg(X + (size_t)s3 * 32 + lane);
#pragma unroll
        for (int j = 0; j < 4; j++) {
            uint2 u = (j == 0) ? u0 : (j == 1) ? u1 : (j == 2) ? u2 : u3;
            float2 a = __half22float2(*reinterpret_cast<__half2*>(&u.x));
            float2 b = __half22float2(*reinterpret_cast<__half2*>(&u.y));
            acc.x += a.x; acc.y += a.y; acc.z += b.x; acc.w += b.y;
        }
    }
    for (; i < end; i++) {
        int s = __ldg(g_esrc + i);
        uint2 u = __ldg(X + (size_t)s * 32 + lane);
        float2 a = __half22float2(*reinterpret_cast<__half2*>(&u.x));
        float2 b = __half22float2(*reinterpret_cast<__half2*>(&u.y));
        acc.x += a.x; acc.y += a.y; acc.z += b.x; acc.w += b.y;
    }
    float nd = g_norm_dst[w];
    acc.x *= nd; acc.y *= nd; acc.z *= nd; acc.w *= nd;
    reinterpret_cast<float4*>(agg)[(size_t)w * 32 + lane] = acc;
}

// ---------------------------------------------------------------------------
// Final CSR aggregation, 64 dims fp16 input: two nodes per warp, + b3 epilogue.
// out[n] = norm_dst[n] * segsum(t) + b3
// ---------------------------------------------------------------------------
__global__ void agg64_f16_kernel(const __half* __restrict__ x,
                                 const float* __restrict__ b3,
                                 float* __restrict__ out) {
    int w = (blockIdx.x * blockDim.x + threadIdx.x) >> 5;
    int sub = (threadIdx.x >> 4) & 1;
    int lane = threadIdx.x & 15;
    int n = w * 2 + sub;
    if (n >= N_NODES) return;
    int beg = g_rowstart[n];
    int end = beg + g_indeg[n];
    const uint2* X = reinterpret_cast<const uint2*>(x);
    float4 acc = make_float4(0.f, 0.f, 0.f, 0.f);

    int i = beg;
    for (; i + 4 <= end; i += 4) {
        int s0 = __ldg(g_esrc + i + 0);
        int s1 = __ldg(g_esrc + i + 1);
        int s2 = __ldg(g_esrc + i + 2);
        int s3 = __ldg(g_esrc + i + 3);
        uint2 u0 = __ldg(X + (size_t)s0 * 16 + lane);
        uint2 u1 = __ldg(X + (size_t)s1 * 16 + lane);
        uint2 u2 = __ldg(X + (size_t)s2 * 16 + lane);
        uint2 u3 = __ldg(X + (size_t)s3 * 16 + lane);
#pragma unroll
        for (int j = 0; j < 4; j++) {
            uint2 u = (j == 0) ? u0 : (j == 1) ? u1 : (j == 2) ? u2 : u3;
            float2 a = __half22float2(*reinterpret_cast<__half2*>(&u.x));
            float2 b = __half22float2(*reinterpret_cast<__half2*>(&u.y));
            acc.x += a.x; acc.y += a.y; acc.z += b.x; acc.w += b.y;
        }
    }
    for (; i < end; i++) {
        int s = __ldg(g_esrc + i);
        uint2 u = __ldg(X + (size_t)s * 16 + lane);
        float2 a = __half22float2(*reinterpret_cast<__half2*>(&u.x));
        float2 b = __half22float2(*reinterpret_cast<__half2*>(&u.y));
        acc.x += a.x; acc.y += a.y; acc.z += b.x; acc.w += b.y;
    }
    float nd = g_norm_dst[n];
    float4 b = __ldg(reinterpret_cast<const float4*>(b3) + lane);
    float4 o;
    o.x = fmaf(acc.x, nd, b.x);
    o.y = fmaf(acc.y, nd, b.y);
    o.z = fmaf(acc.z, nd, b.z);
    o.w = fmaf(acc.w, nd, b.w);
    reinterpret_cast<float4*>(out)[(size_t)n * 16 + lane] = o;
}

// ---------------------------------------------------------------------------
// TF32 helpers
// ---------------------------------------------------------------------------
__device__ __forceinline__ uint32_t f2tf32(float f) {
    uint32_t r;
    asm("cvt.rna.tf32.f32 %0, %1;" : "=r"(r) : "f"(f));
    return r;
}

__device__ __forceinline__ void mma_tf32(float c[4], const uint32_t a[4], const uint32_t b[2]) {
    asm volatile(
        "mma.sync.aligned.m16n8k8.row.col.f32.tf32.tf32.f32 "
        "{%0,%1,%2,%3}, {%4,%5,%6,%7}, {%8,%9}, {%0,%1,%2,%3};"
        : "+f"(c[0]), "+f"(c[1]), "+f"(c[2]), "+f"(c[3])
        : "r"(a[0]), "r"(a[1]), "r"(a[2]), "r"(a[3]), "r"(b[0]), "r"(b[1]));
}

// Stage W (KxN, row-major) transposed into sW[n][k] as tf32. 256 threads.
template <int N>
__device__ __forceinline__ void stage_w(const float* __restrict__ W, uint32_t* sW, int SA, int tid) {
    constexpr int K = 128;
#pragma unroll
    for (int i = tid; i < K * (N / 4); i += 256) {
        int k  = i / (N / 4);
        int nb = i % (N / 4);
        float4 v = __ldg(reinterpret_cast<const float4*>(W + (size_t)k * N) + nb);
        sW[(nb * 4 + 0) * SA + k] = f2tf32(v.x);
        sW[(nb * 4 + 1) * SA + k] = f2tf32(v.y);
        sW[(nb * 4 + 2) * SA + k] = f2tf32(v.z);
        sW[(nb * 4 + 3) * SA + k] = f2tf32(v.w);
    }
}

// One 128x128xN tf32 mma pass from sA, sW into acc[4][N/32][4].
template <int N>
__device__ __forceinline__ void mma_pass(const uint32_t* sA, const uint32_t* sW, int SA,
                                         int rbase, int ncol0, int g, int tg,
                                         float acc[4][N / 32][4]) {
    constexpr int K = 128;
    constexpr int NT = N / 32;
#pragma unroll
    for (int m = 0; m < 4; m++)
#pragma unroll
        for (int n = 0; n < NT; n++) {
            acc[m][n][0] = 0.f; acc[m][n][1] = 0.f; acc[m][n][2] = 0.f; acc[m][n][3] = 0.f;
        }
#pragma unroll
    for (int k0 = 0; k0 < K; k0 += 8) {
        uint32_t a[4][4];
#pragma unroll
        for (int m = 0; m < 4; m++) {
            const uint32_t* base = sA + (rbase + m * 16 + g) * SA + k0 + tg;
            a[m][0] = base[0];
            a[m][1] = base[8 * SA];
            a[m][2] = base[4];
            a[m][3] = base[8 * SA + 4];
        }
        uint32_t b[NT][2];
#pragma unroll
        for (int n = 0; n < NT; n++) {
            const uint32_t* base = sW + (ncol0 + n * 8 + g) * SA + k0 + tg;
            b[n][0] = base[0];
            b[n][1] = base[4];
        }
#pragma unroll
        for (int m = 0; m < 4; m++)
#pragma unroll
            for (int n = 0; n < NT; n++)
                mma_tf32(acc[m][n], a[m], b[n]);
    }
}

// ---------------------------------------------------------------------------
// GEMM1: hh(fp16) = norm_src * relu(agg @ W1 + b1)
// ---------------------------------------------------------------------------
__global__ void __launch_bounds__(256, 1)
gemm1_kernel(const float* __restrict__ in,
             const float* __restrict__ W,
             const float* __restrict__ bias,
             const float* __restrict__ post_scale,
             __half* __restrict__ out) {
    constexpr int K = 128, N = 128, SA = K + 4, ROWS = 128;
    extern __shared__ uint32_t smem[];
    uint32_t* sA = smem;
    uint32_t* sW = smem + ROWS * SA;

    const int tid  = threadIdx.x;
    const int row0 = blockIdx.x * ROWS;

#pragma unroll
    for (int i = tid; i < ROWS * (K / 4); i += 256) {
        int r  = i / (K / 4);
        int kk = i % (K / 4);
        int row = row0 + r;
        float4 v = make_float4(0.f, 0.f, 0.f, 0.f);
        if (row < N_NODES)
            v = __ldg(reinterpret_cast<const float4*>(in + (size_t)row * K) + kk);
        uint32_t* p = sA + r * SA + kk * 4;
        p[0] = f2tf32(v.x); p[1] = f2tf32(v.y); p[2] = f2tf32(v.z); p[3] = f2tf32(v.w);
    }
    stage_w<N>(W, sW, SA, tid);
    __syncthreads();

    const int warp = tid >> 5, lane = tid & 31;
    const int g = lane >> 2, tg = lane & 3;
    const int rbase = (warp >> 2) * 64;
    const int ncol0 = (warp & 3) * (N / 4);

    float acc[4][N / 32][4];
    mma_pass<N>(sA, sW, SA, rbase, ncol0, g, tg, acc);

#pragma unroll
    for (int m = 0; m < 4; m++)
#pragma unroll
        for (int half = 0; half < 2; half++) {
            int row = row0 + rbase + m * 16 + g + half * 8;
            if (row >= N_NODES) continue;
            float ps = __ldg(&post_scale[row]);
#pragma unroll
            for (int n = 0; n < N / 32; n++) {
                int col = ncol0 + n * 8 + 2 * tg;
                float2 bv = *reinterpret_cast<const float2*>(bias + col);
                float ox = fmaxf(acc[m][n][half * 2 + 0] + bv.x, 0.f) * ps;
                float oy = fmaxf(acc[m][n][half * 2 + 1] + bv.y, 0.f) * ps;
                *reinterpret_cast<__half2*>(out + (size_t)row * N + col) =
                    __floats2half2_rn(ox, oy);
            }
        }
}

// ---------------------------------------------------------------------------
// Fused GEMM2+GEMM3:
//   h_tile = relu(agg_tile @ W2 + b2)        (kept in smem as tf32)
//   t_tile = norm_src * (h_tile @ W3)        -> fp16 out (64-wide)
// ---------------------------------------------------------------------------
__global__ void __launch_bounds__(256, 1)
gemm23_kernel(const float* __restrict__ in,
              const float* __restrict__ W2,
              const float* __restrict__ b2,
              const float* __restrict__ W3,
              const float* __restrict__ post_scale,
              __half* __restrict__ out) {
    constexpr int K = 128, N2 = 128, N3 = 64, SA = K + 4, ROWS = 128;
    extern __shared__ uint32_t smem[];
    uint32_t* sA  = smem;                        // [128][SA] agg tile, then h tile
    uint32_t* sW2 = smem + ROWS * SA;            // [128][SA]
    uint32_t* sW3 = smem + 2 * ROWS * SA;        // [64][SA]

    const int tid  = threadIdx.x;
    const int row0 = blockIdx.x * ROWS;

#pragma unroll
    for (int i = tid; i < ROWS * (K / 4); i += 256) {
        int r  = i / (K / 4);
        int kk = i % (K / 4);
        int row = row0 + r;
        float4 v = make_float4(0.f, 0.f, 0.f, 0.f);
        if (row < N_NODES)
            v = __ldg(reinterpret_cast<const float4*>(in + (size_t)row * K) + kk);
        uint32_t* p = sA + r * SA + kk * 4;
        p[0] = f2tf32(v.x); p[1] = f2tf32(v.y); p[2] = f2tf32(v.z); p[3] = f2tf32(v.w);
    }
    stage_w<N2>(W2, sW2, SA, tid);
    stage_w<N3>(W3, sW3, SA, tid);
    __syncthreads();

    const int warp = tid >> 5, lane = tid & 31;
    const int g = lane >> 2, tg = lane & 3;
    const int rbase = (warp >> 2) * 64;
    const int ncol2 = (warp & 3) * (N2 / 4);
    const int ncol3 = (warp & 3) * (N3 / 4);

    // Phase 1: h = relu(agg @ W2 + b2)
    float acc1[4][N2 / 32][4];
    mma_pass<N2>(sA, sW2, SA, rbase, ncol2, g, tg, acc1);
    __syncthreads();   // everyone done reading sA before overwrite

#pragma unroll
    for (int m = 0; m < 4; m++)
#pragma unroll
        for (int half = 0; half < 2; half++) {
            int rloc = rbase + m * 16 + g + half * 8;
#pragma unroll
            for (int n = 0; n < N2 / 32; n++) {
                int col = ncol2 + n * 8 + 2 * tg;
                float2 bv = *reinterpret_cast<const float2*>(b2 + col);
                float hx = fmaxf(acc1[m][n][half * 2 + 0] + bv.x, 0.f);
                float hy = fmaxf(acc1[m][n][half * 2 + 1] + bv.y, 0.f);
                sA[rloc * SA + col]     = f2tf32(hx);
                sA[rloc * SA + col + 1] = f2tf32(hy);
            }
        }
    __syncthreads();

    // Phase 2: t = norm_src * (h @ W3)
    float acc2[4][N3 / 32][4];
    mma_pass<N3>(sA, sW3, SA, rbase, ncol3, g, tg, acc2);

#pragma unroll
    for (int m = 0; m < 4; m++)
#pragma unroll
        for (int half = 0; half < 2; half++) {
            int row = row0 + rbase + m * 16 + g + half * 8;
            if (row >= N_NODES) continue;
            float ps = __ldg(&post_scale[row]);
#pragma unroll
            for (int n = 0; n < N3 / 32; n++) {
                int col = ncol3 + n * 8 + 2 * tg;
                float ox = acc2[m][n][half * 2 + 0] * ps;
                float oy = acc2[m][n][half * 2 + 1] * ps;
                *reinterpret_cast<__half2*>(out + (size_t)row * N3 + col) =
                    __floats2half2_rn(ox, oy);
            }
        }
}

// ---------------------------------------------------------------------------
extern "C" void kernel_launch(void* const* d_in, const int* in_sizes, int n_in,
                              void* d_out, int out_size) {
    const float* features = (const float*)d_in[0];
    const float* W1 = (const float*)d_in[1];
    const float* b1 = (const float*)d_in[2];
    const float* W2 = (const float*)d_in[3];
    const float* b2 = (const float*)d_in[4];
    const float* W3 = (const float*)d_in[5];
    const float* b3 = (const float*)d_in[6];
    const int* src  = (const int*)d_in[7];
    const int* dst  = (const int*)d_in[8];
    const int E = in_sizes[7];
    float* out = (float*)d_out;

    float *agg, *nsrc;
    __half* hh;
    cudaGetSymbolAddress((void**)&agg,  g_agg);
    cudaGetSymbolAddress((void**)&hh,   g_hh);
    cudaGetSymbolAddress((void**)&nsrc, g_norm_src);

    const int SA = 132;
    const int smem1  = (128 + 128) * SA * 4;             // 135168
    const int smem23 = (128 + 128 + 64) * SA * 4;        // 168960
    cudaFuncSetAttribute(gemm1_kernel,
                         cudaFuncAttributeMaxDynamicSharedMemorySize, smem1);
    cudaFuncSetAttribute(gemm23_kernel,
                         cudaFuncAttributeMaxDynamicSharedMemorySize, smem23);

    const int TB = 256;
    const int blocks128 = (N_NODES + 127) / 128;   // 391

    // CSR build (sorted by dst) + norms.
    zero_deg_kernel<<<(N_NODES + TB - 1) / TB, TB>>>();
    deg_kernel<<<(E + TB - 1) / TB, TB>>>(src, dst, E);
    scan1_kernel<<<NB_SCAN, 1024>>>();
    scan3_kernel<<<(N_NODES + TB - 1) / TB, TB>>>();
    place_kernel<<<(E + TB - 1) / TB, TB>>>(src, dst, E);

    // hh = fp16(norm_src * features)
    convert_feat_kernel<<<(N_NODES * DIM / 4 + TB - 1) / TB, TB>>>(features);

    // Layer 1: agg = norm_dst*segsum(hh); hh = fp16(norm_src * relu(agg @ W1 + b1))
    agg128_f16_kernel<<<(N_NODES * 32 + TB - 1) / TB, TB>>>(hh, agg);
    gemm1_kernel<<<blocks128, 256, smem1>>>(agg, W1, b1, nsrc, hh);

    // Layer 2: agg = norm_dst*segsum(hh)
    agg128_f16_kernel<<<(N_NODES * 32 + TB - 1) / TB, TB>>>(hh, agg);

    // Layers 2+3 fused: hh(64-wide fp16) = norm_src * (relu(agg@W2+b2) @ W3)
    gemm23_kernel<<<blocks128, 256, smem23>>>(agg, W2, b2, W3, nsrc, hh);

    // out = norm_dst * segsum(hh) + b3
    agg64_f16_kernel<<<((N_NODES + 1) / 2 * 32 + TB - 1) / TB, TB>>>(hh, b3, out);
}